// round 17
// baseline (speedup 1.0000x reference)
#include <cuda_runtime.h>
#include <cuda_bf16.h>
#include <math.h>
#include <stdint.h>

#define Bd 16
#define Sd 168
#define Nd 200
#define Hd 128
#define Td 24
#define NHd 4
#define DHd 32

#define R_KV (Bd*Sd*Nd)      /* 537600 */
#define R_Q  (Bd*Td*Nd)      /* 76800  */

// ---------------- scratch (static device allocations; no cudaMalloc) ----------------
__device__ __nv_bfloat16 g_query_h[(size_t)R_Q*Hd];
__device__ __nv_bfloat16 g_query_l[(size_t)R_Q*Hd];
__device__ __nv_bfloat16 g_ctx_h[(size_t)R_Q*Hd];
__device__ __nv_bfloat16 g_ctx_l[(size_t)R_Q*Hd];
__device__ __nv_bfloat16 g_xln_h[(size_t)R_Q*Hd];
__device__ __nv_bfloat16 g_xln_l[(size_t)R_Q*Hd];
__device__ __nv_bfloat16 g_h0_h[3200*Hd], g_h0_l[3200*Hd];
__device__ __nv_bfloat16 g_h1_h[3200*Hd], g_h1_l[3200*Hd];
__device__ float g_Q[(size_t)R_Q*Hd];
__device__ float g_KV[(size_t)R_KV*256];   // K in cols 0..127, V in cols 128..255
__device__ float g_comb[(size_t)R_Q*Hd];
__device__ float g_x1[(size_t)R_Q*Hd];
__device__ float g_predpart[(size_t)R_Q*16];
__device__ float g_hWh[Bd*Nd*512];
__device__ float g_G0[Bd*Nd*512];
__device__ float g_G1[Bd*Nd*512];
// transposed/split weights [N,128] bf16 (k contiguous); gates weights gate-interleaved
__device__ __nv_bfloat16 g_Wqt_h[128*128],  g_Wqt_l[128*128];
__device__ __nv_bfloat16 g_Wkvt_h[256*128], g_Wkvt_l[256*128];
__device__ __nv_bfloat16 g_Wtop_h[128*128], g_Wtop_l[128*128];
__device__ __nv_bfloat16 g_Wcct_h[128*128], g_Wcct_l[128*128];
__device__ __nv_bfloat16 g_Wx0t_h[512*128], g_Wx0t_l[512*128];
__device__ __nv_bfloat16 g_Wh0t_h[512*128], g_Wh0t_l[512*128];
__device__ __nv_bfloat16 g_Wx1t_h[512*128], g_Wx1t_l[512*128];
__device__ __nv_bfloat16 g_Wh1t_h[512*128], g_Wh1t_l[512*128];
__device__ float g_bkv[256];
__device__ float g_bcc[128];

// ---------------- helpers ----------------
__device__ __forceinline__ float sigmoidf_(float x) { return 1.f / (1.f + expf(-x)); }

__device__ __forceinline__ void store_split4(float4 v, __nv_bfloat16* hp, __nv_bfloat16* lp) {
    __nv_bfloat16 h0 = __float2bfloat16(v.x), h1 = __float2bfloat16(v.y),
                  h2 = __float2bfloat16(v.z), h3 = __float2bfloat16(v.w);
    __nv_bfloat16 l0 = __float2bfloat16(v.x - __bfloat162float(h0)),
                  l1 = __float2bfloat16(v.y - __bfloat162float(h1)),
                  l2 = __float2bfloat16(v.z - __bfloat162float(h2)),
                  l3 = __float2bfloat16(v.w - __bfloat162float(h3));
    __nv_bfloat162 a, b2, c, d;
    a.x = h0; a.y = h1; b2.x = h2; b2.y = h3;
    c.x = l0; c.y = l1; d.x  = l2; d.y  = l3;
    *(__nv_bfloat162*)hp       = a;
    *(__nv_bfloat162*)(hp + 2) = b2;
    *(__nv_bfloat162*)lp       = c;
    *(__nv_bfloat162*)(lp + 2) = d;
}

__device__ __forceinline__ uint32_t smem_u32(const void* p) {
    uint32_t a;
    asm("{ .reg .u64 t; cvta.to.shared.u64 t, %1; cvt.u32.u64 %0, t; }" : "=r"(a) : "l"(p));
    return a;
}

__device__ __forceinline__ void ldsm4(uint32_t* r, uint32_t addr) {
    asm volatile("ldmatrix.sync.aligned.m8n8.x4.shared.b16 {%0,%1,%2,%3}, [%4];"
        : "=r"(r[0]), "=r"(r[1]), "=r"(r[2]), "=r"(r[3]) : "r"(addr));
}

__device__ __forceinline__ void mma16816(float* c, const uint32_t* a, const uint32_t* b) {
    asm volatile("mma.sync.aligned.m16n8k16.row.col.f32.bf16.bf16.f32 "
        "{%0,%1,%2,%3}, {%4,%5,%6,%7}, {%8,%9}, {%0,%1,%2,%3};"
        : "+f"(c[0]), "+f"(c[1]), "+f"(c[2]), "+f"(c[3])
        : "r"(a[0]), "r"(a[1]), "r"(a[2]), "r"(a[3]), "r"(b[0]), "r"(b[1]));
}

__device__ __forceinline__ void cpa16(uint32_t d, const void* s) {
    asm volatile("cp.async.cg.shared.global [%0], [%1], 16;" :: "r"(d), "l"(s));
}

// ---------------- pipelined bf16 split-precision MMA GEMM (generic, 128x128 tile) ----------------
#define TS   40                         /* row stride in bf16 */
#define TSB  (TS*2)                     /* 80 bytes */
#define TILE_STAGE (128*TSB)            /* 10240 B per tile per stage */
#define STAGE_B (4*TILE_STAGE)          /* 40960 B per stage */
#define GEMM_SMEM (2*STAGE_B)           /* 81920 B */

__device__ __forceinline__ void gemm_issue(uint32_t sb, int buf, int kt,
        const __nv_bfloat16* a0, const __nv_bfloat16* a1,
        const __nv_bfloat16* b0, const __nv_bfloat16* b1, int tid) {
    const __nv_bfloat16* s[4] = {a0, a1, b0, b1};
    uint32_t dst = sb + buf * STAGE_B;
    #pragma unroll
    for (int t4 = 0; t4 < 4; t4++) {
        #pragma unroll
        for (int rep = 0; rep < 2; rep++) {
            int c   = tid + rep * 256;
            int row = c >> 2, seg = c & 3;
            cpa16(dst + t4 * TILE_STAGE + row * TSB + seg * 16,
                  s[t4] + (size_t)row * 128 + kt * 32 + seg * 8);
        }
    }
    asm volatile("cp.async.commit_group;" ::: "memory");
}

// mainloop shared by generic + gates kernels: accumulates acc[4][4][4]
#define GEMM_MAINLOOP(aOff, bOff)                                                        \
    gemm_issue(sb, 0, 0, a0, a1, b0, b1, tid);                                           \
    _Pragma("unroll")                                                                    \
    for (int kt = 0; kt < 4; kt++) {                                                     \
        if (kt < 3) {                                                                    \
            gemm_issue(sb, (kt + 1) & 1, kt + 1, a0, a1, b0, b1, tid);                   \
            asm volatile("cp.async.wait_group 1;" ::: "memory");                         \
        } else {                                                                         \
            asm volatile("cp.async.wait_group 0;" ::: "memory");                         \
        }                                                                                \
        __syncthreads();                                                                 \
        const uint32_t base = sb + (kt & 1) * STAGE_B;                                   \
        const uint32_t aHb = base + aOff;                                                \
        const uint32_t aLb = base + TILE_STAGE + aOff;                                   \
        const uint32_t bHb = base + 2 * TILE_STAGE + bOff;                               \
        const uint32_t bLb = base + 3 * TILE_STAGE + bOff;                               \
        _Pragma("unroll")                                                                \
        for (int kk = 0; kk < 2; kk++) {                                                 \
            const uint32_t kb = kk * 32;                                                 \
            uint32_t ah[4][4], bh[2][4], bl[2][4];                                       \
            _Pragma("unroll")                                                            \
            for (int mi = 0; mi < 4; mi++) ldsm4(ah[mi], aHb + mi * (16 * TSB) + kb);    \
            _Pragma("unroll")                                                            \
            for (int pi = 0; pi < 2; pi++) ldsm4(bh[pi], bHb + pi * (16 * TSB) + kb);    \
            _Pragma("unroll")                                                            \
            for (int pi = 0; pi < 2; pi++) ldsm4(bl[pi], bLb + pi * (16 * TSB) + kb);    \
            _Pragma("unroll")                                                            \
            for (int mi = 0; mi < 4; mi++)                                               \
                _Pragma("unroll")                                                        \
                for (int ni = 0; ni < 4; ni++) {                                         \
                    const uint32_t* bhf = &bh[ni >> 1][(ni & 1) * 2];                    \
                    const uint32_t* blf = &bl[ni >> 1][(ni & 1) * 2];                    \
                    mma16816(acc[mi][ni], ah[mi], bhf);                                  \
                    mma16816(acc[mi][ni], ah[mi], blf);                                  \
                }                                                                        \
            _Pragma("unroll")                                                            \
            for (int mi = 0; mi < 4; mi++) {                                             \
                uint32_t alt[4];                                                         \
                ldsm4(alt, aLb + mi * (16 * TSB) + kb);                                  \
                _Pragma("unroll")                                                        \
                for (int ni = 0; ni < 4; ni++)                                           \
                    mma16816(acc[mi][ni], alt, &bh[ni >> 1][(ni & 1) * 2]);              \
            }                                                                            \
        }                                                                                \
        __syncthreads();                                                                 \
    }

__global__ void __launch_bounds__(256, 2)
gemm_mma_kernel(const __nv_bfloat16* __restrict__ Ah, const __nv_bfloat16* __restrict__ Al,
                const __nv_bfloat16* __restrict__ Bh, const __nv_bfloat16* __restrict__ Bl,
                float* __restrict__ C, const float* __restrict__ bias, int ldc, int accum)
{
    extern __shared__ __align__(16) char dynsm[];
    const uint32_t sb = smem_u32(dynsm);
    const int tid  = threadIdx.x;
    const int row0 = blockIdx.y * 128;
    const int col0 = blockIdx.x * 128;

    const __nv_bfloat16* a0 = Ah + (size_t)row0 * 128;
    const __nv_bfloat16* a1 = Al + (size_t)row0 * 128;
    const __nv_bfloat16* b0 = Bh + (size_t)col0 * 128;
    const __nv_bfloat16* b1 = Bl + (size_t)col0 * 128;

    const int wid  = tid >> 5;
    const int lane = tid & 31;
    const int m0w  = (wid & 1) * 64;
    const int n0w  = (wid >> 1) * 32;

    const uint32_t aOff = (uint32_t)((m0w + (lane & 15)) * TS + (lane >> 4) * 8) * 2;
    const int bg = lane >> 3;
    const uint32_t bOff = (uint32_t)((n0w + (bg >> 1) * 8 + (lane & 7)) * TS + (bg & 1) * 8) * 2;

    float acc[4][4][4];
    #pragma unroll
    for (int mi = 0; mi < 4; mi++)
        #pragma unroll
        for (int ni = 0; ni < 4; ni++)
            #pragma unroll
            for (int q = 0; q < 4; q++) acc[mi][ni][q] = 0.f;

    GEMM_MAINLOOP(aOff, bOff)

    const int mrow = lane >> 2;
    const int ncol = (lane & 3) * 2;
    #pragma unroll
    for (int mi = 0; mi < 4; mi++) {
        const int rg = row0 + m0w + mi * 16 + mrow;
        #pragma unroll
        for (int ni = 0; ni < 4; ni++) {
            const int cg = col0 + n0w + ni * 8 + ncol;
            float b0v = bias ? bias[cg] : 0.f;
            float b1v = bias ? bias[cg + 1] : 0.f;
            float* p0 = C + (size_t)rg * ldc + cg;
            float* p1 = C + (size_t)(rg + 8) * ldc + cg;
            float2 o0 = make_float2(acc[mi][ni][0] + b0v, acc[mi][ni][1] + b1v);
            float2 o1 = make_float2(acc[mi][ni][2] + b0v, acc[mi][ni][3] + b1v);
            if (accum) {
                float2 c0v = *(const float2*)p0;
                float2 c1v = *(const float2*)p1;
                o0.x += c0v.x; o0.y += c0v.y;
                o1.x += c1v.x; o1.y += c1v.y;
            }
            *(float2*)p0 = o0;
            *(float2*)p1 = o1;
        }
    }
}

// ---------------- gates GEMM with fused LSTM-cell epilogue ----------------
// Weights gate-interleaved: output col c = h*4 + gate. Per warp fragment, the 4 gates of
// one h sit on adjacent lanes (q, q^1) -> shfl_xor(1) assembles (i,f,g,o) on even-q lanes.
// mode 0 (layer 0): x = cell(...)  -> x1out
// mode 1 (layer 1): x = cell(...) + resid; predpart[r*16 + tile] = partial x . outW
__global__ void __launch_bounds__(256, 2)
gemm_gates_kernel(const __nv_bfloat16* __restrict__ Ah, const __nv_bfloat16* __restrict__ Al,
                  const __nv_bfloat16* __restrict__ Bh, const __nv_bfloat16* __restrict__ Bl,
                  const float* __restrict__ G, const float* __restrict__ cin,
                  const float* __restrict__ resid, float* __restrict__ x1out,
                  float* __restrict__ predpart, const float* __restrict__ outW, int mode)
{
    extern __shared__ __align__(16) char dynsm[];
    const uint32_t sb = smem_u32(dynsm);
    const int tid  = threadIdx.x;
    const int row0 = blockIdx.y * 128;
    const int col0 = blockIdx.x * 128;

    const __nv_bfloat16* a0 = Ah + (size_t)row0 * 128;
    const __nv_bfloat16* a1 = Al + (size_t)row0 * 128;
    const __nv_bfloat16* b0 = Bh + (size_t)col0 * 128;
    const __nv_bfloat16* b1 = Bl + (size_t)col0 * 128;

    const int wid  = tid >> 5;
    const int lane = tid & 31;
    const int m0w  = (wid & 1) * 64;
    const int n0w  = (wid >> 1) * 32;

    const uint32_t aOff = (uint32_t)((m0w + (lane & 15)) * TS + (lane >> 4) * 8) * 2;
    const int bgr = lane >> 3;
    const uint32_t bOff = (uint32_t)((n0w + (bgr >> 1) * 8 + (lane & 7)) * TS + (bgr & 1) * 8) * 2;

    float acc[4][4][4];
    #pragma unroll
    for (int mi = 0; mi < 4; mi++)
        #pragma unroll
        for (int ni = 0; ni < 4; ni++)
            #pragma unroll
            for (int q = 0; q < 4; q++) acc[mi][ni][q] = 0.f;

    GEMM_MAINLOOP(aOff, bOff)

    // ---- fused epilogue ----
    const int mrow = lane >> 2;
    const int q    = lane & 3;
    const bool evenq = (q & 1) == 0;
    float spart[4][2];
    #pragma unroll
    for (int mi = 0; mi < 4; mi++) { spart[mi][0] = 0.f; spart[mi][1] = 0.f; }

    #pragma unroll
    for (int mi = 0; mi < 4; mi++) {
        const int r0g = row0 + m0w + mi * 16 + mrow;
        const int r1g = r0g + 8;
        const int bA = r0g / (Td * Nd), nA = r0g % Nd;
        const int bB = r1g / (Td * Nd), nB = r1g % Nd;
        const float* GA = G + ((size_t)(bA * Nd + nA)) * 512;
        const float* GB = G + ((size_t)(bB * Nd + nB)) * 512;
        const float* cA = cin + ((size_t)(bA * Nd + nA)) * 128;
        const float* cB = cin + ((size_t)(bB * Nd + nB)) * 128;
        #pragma unroll
        for (int ni = 0; ni < 4; ni++) {
            const int cg = col0 + n0w + ni * 8 + q * 2;
            float v0 = acc[mi][ni][0] + GA[cg];
            float v1 = acc[mi][ni][1] + GA[cg + 1];
            float v2 = acc[mi][ni][2] + GB[cg];
            float v3 = acc[mi][ni][3] + GB[cg + 1];
            float p0 = __shfl_xor_sync(~0u, v0, 1);
            float p1 = __shfl_xor_sync(~0u, v1, 1);
            float p2 = __shfl_xor_sync(~0u, v2, 1);
            float p3 = __shfl_xor_sync(~0u, v3, 1);
            if (evenq) {
                const int h = cg >> 2;
                // rows r0g: i=v0 f=v1 g=p0 o=p1 ; r1g: i=v2 f=v3 g=p2 o=p3
                float cnA = sigmoidf_(v1) * cA[h] + sigmoidf_(v0) * tanhf(p0);
                float xA  = sigmoidf_(p1) * tanhf(cnA);
                float cnB = sigmoidf_(v3) * cB[h] + sigmoidf_(v2) * tanhf(p2);
                float xB  = sigmoidf_(p3) * tanhf(cnB);
                if (mode == 0) {
                    x1out[(size_t)r0g * 128 + h] = xA;
                    x1out[(size_t)r1g * 128 + h] = xB;
                } else {
                    xA += resid[(size_t)r0g * 128 + h];
                    xB += resid[(size_t)r1g * 128 + h];
                    float w = outW[h];
                    spart[mi][0] += xA * w;
                    spart[mi][1] += xB * w;
                }
            }
        }
    }
    if (mode == 1) {
        const int idx = (col0 >> 7) * 4 + (wid >> 1);
        #pragma unroll
        for (int mi = 0; mi < 4; mi++) {
            float s0 = spart[mi][0] + __shfl_xor_sync(~0u, spart[mi][0], 2);
            float s1 = spart[mi][1] + __shfl_xor_sync(~0u, spart[mi][1], 2);
            if (q == 0) {
                const int r0g = row0 + m0w + mi * 16 + mrow;
                predpart[(size_t)r0g * 16 + idx] = s0;
                predpart[(size_t)(r0g + 8) * 16 + idx] = s1;
            }
        }
    }
}

__global__ void preds_reduce_kernel(const float* __restrict__ pp, const float* __restrict__ ob,
                                    float* __restrict__ out) {
    int r = blockIdx.x * 256 + threadIdx.x;
    if (r >= R_Q) return;
    const float* p = pp + (size_t)r * 16;
    float s = ob[0];
    #pragma unroll
    for (int i = 0; i < 16; i++) s += p[i];
    out[r] = s;
}

// ---------------- fused KV GEMM: C[128 x 256] = enc_fp32 @ Wkv^T, A split in registers ----------------
#define KV_ATILE (128*TSB)
#define KV_BTILE (256*TSB)
#define KV_STAGE (2*KV_ATILE + 2*KV_BTILE)
#define KV_SMEM  (2*KV_STAGE)

__device__ __forceinline__ void kv_issueB(uint32_t sb, int buf, int kt,
        const __nv_bfloat16* b0, const __nv_bfloat16* b1, int tid) {
    uint32_t dst = sb + buf * KV_STAGE + 2 * KV_ATILE;
    #pragma unroll
    for (int t4 = 0; t4 < 2; t4++) {
        const __nv_bfloat16* src = t4 ? b1 : b0;
        #pragma unroll
        for (int rep = 0; rep < 4; rep++) {
            int c = tid + rep * 256;
            int row = c >> 2, seg = c & 3;
            cpa16(dst + t4 * KV_BTILE + row * TSB + seg * 16,
                  src + (size_t)row * 128 + kt * 32 + seg * 8);
        }
    }
    asm volatile("cp.async.commit_group;" ::: "memory");
}

__device__ __forceinline__ void kv_loadA(float4* ar, const float* aP, int kt, int tid) {
    #pragma unroll
    for (int rep = 0; rep < 2; rep++) {
        int c = tid + rep * 256;
        int row = c >> 2, seg = c & 3;
        const float* p = aP + (size_t)row * 128 + kt * 32 + seg * 8;
        ar[rep * 2 + 0] = *(const float4*)p;
        ar[rep * 2 + 1] = *(const float4*)(p + 4);
    }
}

__device__ __forceinline__ void kv_stsA(uint32_t sb, int buf, const float4* ar, int tid) {
    uint32_t dh = sb + buf * KV_STAGE;
    uint32_t dl = dh + KV_ATILE;
    #pragma unroll
    for (int rep = 0; rep < 2; rep++) {
        int c = tid + rep * 256;
        int row = c >> 2, seg = c & 3;
        __nv_bfloat16 hb[8], lb[8];
        const float* f = (const float*)&ar[rep * 2];
        #pragma unroll
        for (int j = 0; j < 8; j++) {
            hb[j] = __float2bfloat16(f[j]);
            lb[j] = __float2bfloat16(f[j] - __bfloat162float(hb[j]));
        }
        uint32_t off = row * TSB + seg * 16;
        asm volatile("st.shared.v4.b32 [%0], {%1,%2,%3,%4};" :: "r"(dh + off),
            "r"(*(const uint32_t*)&hb[0]), "r"(*(const uint32_t*)&hb[2]),
            "r"(*(const uint32_t*)&hb[4]), "r"(*(const uint32_t*)&hb[6]));
        asm volatile("st.shared.v4.b32 [%0], {%1,%2,%3,%4};" :: "r"(dl + off),
            "r"(*(const uint32_t*)&lb[0]), "r"(*(const uint32_t*)&lb[2]),
            "r"(*(const uint32_t*)&lb[4]), "r"(*(const uint32_t*)&lb[6]));
    }
}

__global__ void __launch_bounds__(256, 1)
gemm_kv_kernel(const float* __restrict__ A,
               const __nv_bfloat16* __restrict__ Bh, const __nv_bfloat16* __restrict__ Bl,
               float* __restrict__ C, const float* __restrict__ bias)
{
    extern __shared__ __align__(16) char dynsm[];
    const uint32_t sb = smem_u32(dynsm);
    const int tid  = threadIdx.x;
    const int row0 = blockIdx.x * 128;
    const float* aP = A + (size_t)row0 * 128;

    const int wid  = tid >> 5;
    const int lane = tid & 31;
    const int m0w  = (wid & 1) * 64;
    const int n0w  = (wid >> 1) * 64;

    const uint32_t aOff = (uint32_t)((m0w + (lane & 15)) * TS + (lane >> 4) * 8) * 2;
    const int bg = lane >> 3;
    const uint32_t bOff = (uint32_t)((n0w + (bg >> 1) * 8 + (lane & 7)) * TS + (bg & 1) * 8) * 2;

    float acc[4][8][4];
    #pragma unroll
    for (int mi = 0; mi < 4; mi++)
        #pragma unroll
        for (int ni = 0; ni < 8; ni++)
            #pragma unroll
            for (int q = 0; q < 4; q++) acc[mi][ni][q] = 0.f;

    float4 ar[4];
    kv_loadA(ar, aP, 0, tid);
    kv_issueB(sb, 0, 0, Bh, Bl, tid);
    kv_stsA(sb, 0, ar, tid);
    kv_loadA(ar, aP, 1, tid);
    kv_issueB(sb, 1, 1, Bh, Bl, tid);

    #pragma unroll
    for (int kt = 0; kt < 4; kt++) {
        if (kt < 3) asm volatile("cp.async.wait_group 1;" ::: "memory");
        else        asm volatile("cp.async.wait_group 0;" ::: "memory");
        __syncthreads();

        const uint32_t base = sb + (kt & 1) * KV_STAGE;
        const uint32_t aHb = base + aOff;
        const uint32_t aLb = base + KV_ATILE + aOff;
        const uint32_t bHb = base + 2 * KV_ATILE + bOff;
        const uint32_t bLb = base + 2 * KV_ATILE + KV_BTILE + bOff;

        #pragma unroll
        for (int kk = 0; kk < 2; kk++) {
            const uint32_t kb = kk * 32;
            uint32_t ah[4][4], bh[4][4], bl[4][4];
            #pragma unroll
            for (int mi = 0; mi < 4; mi++) ldsm4(ah[mi], aHb + mi * (16 * TSB) + kb);
            #pragma unroll
            for (int pi = 0; pi < 4; pi++) ldsm4(bh[pi], bHb + pi * (16 * TSB) + kb);
            #pragma unroll
            for (int pi = 0; pi < 4; pi++) ldsm4(bl[pi], bLb + pi * (16 * TSB) + kb);
            #pragma unroll
            for (int mi = 0; mi < 4; mi++)
                #pragma unroll
                for (int ni = 0; ni < 8; ni++) {
                    const uint32_t* bhf = &bh[ni >> 1][(ni & 1) * 2];
                    const uint32_t* blf = &bl[ni >> 1][(ni & 1) * 2];
                    mma16816(acc[mi][ni], ah[mi], bhf);
                    mma16816(acc[mi][ni], ah[mi], blf);
                }
            #pragma unroll
            for (int mi = 0; mi < 4; mi++) {
                uint32_t alt[4];
                ldsm4(alt, aLb + mi * (16 * TSB) + kb);
                #pragma unroll
                for (int ni = 0; ni < 8; ni++)
                    mma16816(acc[mi][ni], alt, &bh[ni >> 1][(ni & 1) * 2]);
            }
        }
        __syncthreads();

        if (kt < 3) {
            kv_stsA(sb, (kt + 1) & 1, ar, tid);
            if (kt < 2) {
                kv_loadA(ar, aP, kt + 2, tid);
                kv_issueB(sb, kt & 1, kt + 2, Bh, Bl, tid);
            }
        }
    }

    const int mrow = lane >> 2;
    const int ncol = (lane & 3) * 2;
    #pragma unroll
    for (int mi = 0; mi < 4; mi++) {
        const int rg = row0 + m0w + mi * 16 + mrow;
        #pragma unroll
        for (int ni = 0; ni < 8; ni++) {
            const int cg = n0w + ni * 8 + ncol;
            float b0v = bias[cg], b1v = bias[cg + 1];
            float* p0 = C + (size_t)rg * 256 + cg;
            float* p1 = C + (size_t)(rg + 8) * 256 + cg;
            *(float2*)p0 = make_float2(acc[mi][ni][0] + b0v, acc[mi][ni][1] + b1v);
            *(float2*)p1 = make_float2(acc[mi][ni][2] + b0v, acc[mi][ni][3] + b1v);
        }
    }
}

// ---------------- weight prep ----------------
// mode 0: plain transpose+split. mode 1: gate-interleave output col n' = (n&127)*4 | (n>>7).
__global__ void wsplit_kernel(const float* __restrict__ W, int N,
                              __nv_bfloat16* __restrict__ th, __nv_bfloat16* __restrict__ tl,
                              int mode) {
    __shared__ float t[32][33];
    int nb = blockIdx.x * 32, kb = blockIdx.y * 32;
    int tx = threadIdx.x, ty = threadIdx.y;
    #pragma unroll
    for (int i = 0; i < 32; i += 8)
        t[ty + i][tx] = W[(size_t)(kb + ty + i) * N + nb + tx];
    __syncthreads();
    #pragma unroll
    for (int i = 0; i < 32; i += 8) {
        int n = nb + ty + i, k = kb + tx;
        int n2 = mode ? (((n & 127) << 2) | (n >> 7)) : n;
        float v = t[tx][ty + i];
        __nv_bfloat16 h = __float2bfloat16(v);
        th[n2 * 128 + k] = h;
        tl[n2 * 128 + k] = __float2bfloat16(v - __bfloat162float(h));
    }
}

__global__ void bkv_kernel(const float* __restrict__ bk, const float* __restrict__ bv) {
    int i = threadIdx.x;
    g_bkv[i] = (i < 128) ? bk[i] : bv[i - 128];
}

__global__ void wcct_kernel(const float* __restrict__ Wo, const float* __restrict__ ctxW) {
    int k = blockIdx.x, n = threadIdx.x;
    float s = 0.f;
    #pragma unroll 4
    for (int j = 0; j < 128; j++)
        s += Wo[k * 128 + j] * ctxW[(128 + j) * 128 + n];
    __nv_bfloat16 h = __float2bfloat16(s);
    g_Wcct_h[n * 128 + k] = h;
    g_Wcct_l[n * 128 + k] = __float2bfloat16(s - __bfloat162float(h));
}

__global__ void bcc_kernel(const float* __restrict__ bo, const float* __restrict__ ctxW,
                           const float* __restrict__ ctxb) {
    int c = threadIdx.x;
    float s = ctxb[c];
    for (int k = 0; k < 128; k++) s += bo[k] * ctxW[(128 + k) * 128 + c];
    g_bcc[c] = s;
}

__global__ void convert_split_kernel(const float* __restrict__ x,
                                     __nv_bfloat16* __restrict__ h, __nv_bfloat16* __restrict__ l,
                                     int n4) {
    int i = blockIdx.x * blockDim.x + threadIdx.x;
    if (i >= n4) return;
    float4 v = ((const float4*)x)[i];
    store_split4(v, h + (size_t)i * 4, l + (size_t)i * 4);
}

__global__ void build_query_kernel(const float* __restrict__ sq, const float* __restrict__ h1) {
    int i = blockIdx.x * blockDim.x + threadIdx.x;
    if (i >= R_Q * Hd / 4) return;
    int c4 = (i & 31) << 2;
    int r  = i >> 5;
    int t  = (r / Nd) % Td;
    int b  = r / (Td * Nd);
    int n  = r % Nd;
    float4 a  = *(const float4*)(sq + t * Hd + c4);
    float4 hh = *(const float4*)(h1 + ((size_t)(b * Nd + n)) * Hd + c4);
    float4 v  = make_float4(a.x + hh.x, a.y + hh.y, a.z + hh.z, a.w + hh.w);
    store_split4(v, g_query_h + (size_t)r * Hd + c4, g_query_l + (size_t)r * Hd + c4);
}

// ---------------- attention: one block per (b,n) ----------------
#define ATTN_SMEM ((24*132 + 168*132 + 96*168) * 4)

__global__ void __launch_bounds__(256) attn_kernel(
    const float* __restrict__ Q, const float* __restrict__ KV,
    float* __restrict__ attn_out,
    __nv_bfloat16* __restrict__ ctx_h, __nv_bfloat16* __restrict__ ctx_l)
{
    const int n = blockIdx.x;
    const int b = blockIdx.y;
    extern __shared__ __align__(16) char dynsm[];
    float* sm = (float*)dynsm;
    float* sQ = sm;
    float* sK = sm + 24*132;
    float* sS = sK + 168*132;
    const int tid = threadIdx.x;

    {
        const float* qb = Q + ((size_t)(b * Td) * Nd + n) * Hd;
        for (int i = tid; i < Td * 32; i += 256) {
            int t = i >> 5, c4 = (i & 31) << 2;
            *(float4*)&sQ[t*132 + c4] = *(const float4*)(qb + (size_t)t * Nd * Hd + c4);
        }
    }
    {
        const float* kb = KV + ((size_t)(b * Sd) * Nd + n) * 256;
        for (int i = tid; i < Sd * 32; i += 256) {
            int s = i >> 5, c4 = (i & 31) << 2;
            *(float4*)&sK[s*132 + c4] = *(const float4*)(kb + (size_t)s * Nd * 256 + c4);
        }
    }
    __syncthreads();

    {
        const int hg  = tid >> 6;
        const int i_t = (tid >> 3) & 7;
        const int j_s = tid & 7;
        float acc[3][21];
        #pragma unroll
        for (int a = 0; a < 3; a++)
            #pragma unroll
            for (int c = 0; c < 21; c++) acc[a][c] = 0.f;
        #pragma unroll
        for (int d4 = 0; d4 < 8; d4++) {
            float4 q[3];
            #pragma unroll
            for (int a = 0; a < 3; a++)
                q[a] = *(const float4*)&sQ[(i_t + 8*a)*132 + hg*32 + d4*4];
            #pragma unroll
            for (int c = 0; c < 21; c++) {
                float4 k = *(const float4*)&sK[(j_s + 8*c)*132 + hg*32 + d4*4];
                #pragma unroll
                for (int a = 0; a < 3; a++)
                    acc[a][c] += q[a].x*k.x + q[a].y*k.y + q[a].z*k.z + q[a].w*k.w;
            }
        }
        const float scale = 0.17677669529663687f;
        #pragma unroll
        for (int a = 0; a < 3; a++)
            #pragma unroll
            for (int c = 0; c < 21; c++)
                sS[((i_t + 8*a)*4 + hg)*168 + (j_s + 8*c)] = acc[a][c] * scale;
    }
    __syncthreads();

    {
        const float* vb = KV + ((size_t)(b * Sd) * Nd + n) * 256 + 128;
        for (int i = tid; i < Sd * 32; i += 256) {
            int s = i >> 5, c4 = (i & 31) << 2;
            *(float4*)&sK[s*132 + c4] = *(const float4*)(vb + (size_t)s * Nd * 256 + c4);
        }
    }

    {
        const int w = tid >> 5, lane = tid & 31;
        for (int rr = 0; rr < 12; rr++) {
            int row = w + (rr << 3);
            float* Sr = sS + row * 168;
            float vals[6];
            float vmax = -1e30f;
            #pragma unroll
            for (int k = 0; k < 6; k++) {
                int s = lane + (k << 5);
                vals[k] = (s < 168) ? Sr[s] : -1e30f;
                vmax = fmaxf(vmax, vals[k]);
            }
            #pragma unroll
            for (int o = 16; o > 0; o >>= 1) vmax = fmaxf(vmax, __shfl_xor_sync(~0u, vmax, o));
            float sum = 0.f;
            #pragma unroll
            for (int k = 0; k < 6; k++) {
                int s = lane + (k << 5);
                float e = (s < 168) ? expf(vals[k] - vmax) : 0.f;
                vals[k] = e; sum += e;
            }
            #pragma unroll
            for (int o = 16; o > 0; o >>= 1) sum += __shfl_xor_sync(~0u, sum, o);
            float inv = 1.f / sum;
            int t = row >> 2, h = row & 3;
            float* outp = attn_out + ((((size_t)(b * Td + t) * NHd + h) * Nd + n) * Sd);
            #pragma unroll
            for (int k = 0; k < 6; k++) {
                int s = lane + (k << 5);
                if (s < 168) { float p = vals[k] * inv; Sr[s] = p; outp[s] = p; }
            }
        }
    }
    __syncthreads();

    {
        const int cq = tid & 31;
        const int tg = tid >> 5;
        const int c0 = cq << 2;
        const int h  = c0 >> 5;
        float acc2[3][4];
        #pragma unroll
        for (int a = 0; a < 3; a++)
            #pragma unroll
            for (int j = 0; j < 4; j++) acc2[a][j] = 0.f;
        #pragma unroll 4
        for (int s = 0; s < 168; s++) {
            float4 v = *(const float4*)&sK[s*132 + c0];
            #pragma unroll
            for (int a = 0; a < 3; a++) {
                int t = tg + (a << 3);
                float p = sS[(t*4 + h)*168 + s];
                acc2[a][0] += p * v.x; acc2[a][1] += p * v.y;
                acc2[a][2] += p * v.z; acc2[a][3] += p * v.w;
            }
        }
        #pragma unroll
        for (int a = 0; a < 3; a++) {
            int t = tg + (a << 3);
            size_t base = ((size_t)(b * Td + t) * Nd + n) * Hd + c0;
            float4 v = make_float4(acc2[a][0], acc2[a][1], acc2[a][2], acc2[a][3]);
            store_split4(v, ctx_h + base, ctx_l + base);
        }
    }
}

// ---------------- layernorm -> split bf16 ----------------
__global__ void ln_kernel(const float* __restrict__ x, const float* __restrict__ g,
                          const float* __restrict__ bt,
                          __nv_bfloat16* __restrict__ yh, __nv_bfloat16* __restrict__ yl) {
    int w = threadIdx.x >> 5, lane = threadIdx.x & 31;
    int row = blockIdx.x * 8 + w;
    const float* xr = x + (size_t)row * 128;
    float4 v = *(const float4*)(xr + lane * 4);
    float s  = v.x + v.y + v.z + v.w;
    float sq = v.x*v.x + v.y*v.y + v.z*v.z + v.w*v.w;
    #pragma unroll
    for (int o = 16; o > 0; o >>= 1) {
        s  += __shfl_xor_sync(~0u, s,  o);
        sq += __shfl_xor_sync(~0u, sq, o);
    }
    float m   = s * (1.f / 128.f);
    float var = sq * (1.f / 128.f) - m * m;
    float inv = rsqrtf(var + 1e-5f);
    float4 gg = *(const float4*)(g + lane * 4);
    float4 bb = *(const float4*)(bt + lane * 4);
    float4 o4;
    o4.x = (v.x - m) * inv * gg.x + bb.x;
    o4.y = (v.y - m) * inv * gg.y + bb.y;
    o4.z = (v.z - m) * inv * gg.z + bb.z;
    o4.w = (v.w - m) * inv * gg.w + bb.w;
    store_split4(o4, yh + (size_t)row * 128 + lane * 4, yl + (size_t)row * 128 + lane * 4);
}

// ---------------- G[b,m,:] = sum_n adj[m,n]*hWh[b,n,:] + bias (bias gate-interleaved lookup) ----------------
__global__ void agg_kernel(const float* __restrict__ adj, const float* __restrict__ hWh,
                           const float* __restrict__ bv, float* __restrict__ G) {
    __shared__ float sA[8][200];
    int b = blockIdx.y, m0 = blockIdx.x * 8;
    int tid = threadIdx.x;
    for (int i = tid; i < 8 * 200; i += 512) {
        int m = i / 200, nn = i % 200;
        sA[m][nn] = adj[(m0 + m) * 200 + nn];
    }
    __syncthreads();
    int c = tid;
    float acc[8];
    #pragma unroll
    for (int m = 0; m < 8; m++) acc[m] = 0.f;
    const float* hb = hWh + (size_t)b * 200 * 512 + c;
    for (int nn = 0; nn < 200; nn++) {
        float v = hb[(size_t)nn * 512];
        #pragma unroll
        for (int m = 0; m < 8; m++) acc[m] += sA[m][nn] * v;
    }
    float bb = bv[((c & 3) << 7) | (c >> 2)];   // interleaved col -> original gate*128+h
    #pragma unroll
    for (int m = 0; m < 8; m++)
        G[((size_t)b * 200 + m0 + m) * 512 + c] = acc[m] + bb;
}

// ---------------- launch ----------------
#define GS(p, sym) cudaGetSymbolAddress((void**)&p, sym)

extern "C" void kernel_launch(void* const* d_in, const int* in_sizes, int n_in,
                              void* d_out, int out_size) {
    const float* enc  = (const float*)d_in[0];
    const float* h0   = (const float*)d_in[1];
    const float* c0   = (const float*)d_in[2];
    const float* h1   = (const float*)d_in[3];
    const float* c1   = (const float*)d_in[4];
    const float* adj  = (const float*)d_in[5];
    const float* sq   = (const float*)d_in[6];
    const float* Wq   = (const float*)d_in[7];
    const float* bq   = (const float*)d_in[8];
    const float* Wk   = (const float*)d_in[9];
    const float* bk   = (const float*)d_in[10];
    const float* Wv   = (const float*)d_in[11];
    const float* bv   = (const float*)d_in[12];
    const float* Wo   = (const float*)d_in[13];
    const float* bo   = (const float*)d_in[14];
    const float* ctxW = (const float*)d_in[15];
    const float* ctxb = (const float*)d_in[16];
    const float* Wx0  = (const float*)d_in[17];
    const float* Wh0  = (const float*)d_in[18];
    const float* b0   = (const float*)d_in[19];
    const float* lng0 = (const float*)d_in[20];
    const float* lnb0 = (const float*)d_in[21];
    const float* Wx1  = (const float*)d_in[22];
    const float* Wh1  = (const float*)d_in[23];
    const float* b1   = (const float*)d_in[24];
    const float* lng1 = (const float*)d_in[25];
    const float* lnb1 = (const float*)d_in[26];
    const float* outW = (const float*)d_in[27];
    const float* outb = (const float*)d_in[28];

    float* out      = (float*)d_out;
    float* attn_out = out + R_Q;

    __nv_bfloat16 *pQh, *pQl, *pCh, *pCl, *pXh, *pXl;
    __nv_bfloat16 *pH0h, *pH0l, *pH1h, *pH1l;
    __nv_bfloat16 *pWqh, *pWql, *pWkvh, *pWkvl, *pWth, *pWtl, *pWcch, *pWccl;
    __nv_bfloat16 *pWx0h, *pWx0l, *pWh0h, *pWh0l, *pWx1h, *pWx1l, *pWh1h, *pWh1l;
    float *pQf, *pKV, *pComb, *pX1, *pPP, *pHWh, *pG0, *pG1, *pBkv, *pBcc;
    GS(pQh, g_query_h); GS(pQl, g_query_l);
    GS(pCh, g_ctx_h);   GS(pCl, g_ctx_l);
    GS(pXh, g_xln_h);   GS(pXl, g_xln_l);
    GS(pH0h, g_h0_h);   GS(pH0l, g_h0_l);
    GS(pH1h, g_h1_h);   GS(pH1l, g_h1_l);
    GS(pWqh, g_Wqt_h);  GS(pWql, g_Wqt_l);
    GS(pWkvh, g_Wkvt_h); GS(pWkvl, g_Wkvt_l);
    GS(pWth, g_Wtop_h); GS(pWtl, g_Wtop_l);
    GS(pWcch, g_Wcct_h); GS(pWccl, g_Wcct_l);
    GS(pWx0h, g_Wx0t_h); GS(pWx0l, g_Wx0t_l);
    GS(pWh0h, g_Wh0t_h); GS(pWh0l, g_Wh0t_l);
    GS(pWx1h, g_Wx1t_h); GS(pWx1l, g_Wx1t_l);
    GS(pWh1h, g_Wh1t_h); GS(pWh1l, g_Wh1t_l);
    GS(pQf, g_Q);       GS(pKV, g_KV);
    GS(pComb, g_comb);  GS(pX1, g_x1);   GS(pPP, g_predpart);
    GS(pHWh, g_hWh);    GS(pG0, g_G0);   GS(pG1, g_G1);
    GS(pBkv, g_bkv);    GS(pBcc, g_bcc);

    cudaFuncSetAttribute(gemm_mma_kernel,   cudaFuncAttributeMaxDynamicSharedMemorySize, GEMM_SMEM);
    cudaFuncSetAttribute(gemm_gates_kernel, cudaFuncAttributeMaxDynamicSharedMemorySize, GEMM_SMEM);
    cudaFuncSetAttribute(gemm_kv_kernel,    cudaFuncAttributeMaxDynamicSharedMemorySize, KV_SMEM);
    cudaFuncSetAttribute(attn_kernel,       cudaFuncAttributeMaxDynamicSharedMemorySize, ATTN_SMEM);

    // --- weight prep (tiled transpose + split; gates weights gate-interleaved) ---
    wsplit_kernel<<<dim3(4, 4),  dim3(32, 8)>>>(Wk, 128, pWkvh, pWkvl, 0);
    wsplit_kernel<<<dim3(4, 4),  dim3(32, 8)>>>(Wv, 128, pWkvh + 128*128, pWkvl + 128*128, 0);
    bkv_kernel<<<1, 256>>>(bk, bv);
    wsplit_kernel<<<dim3(4, 4),  dim3(32, 8)>>>(Wq, 128, pWqh, pWql, 0);
    wsplit_kernel<<<dim3(4, 4),  dim3(32, 8)>>>(ctxW, 128, pWth, pWtl, 0);
    wcct_kernel<<<128, 128>>>(Wo, ctxW);
    bcc_kernel<<<1, 128>>>(bo, ctxW, ctxb);
    wsplit_kernel<<<dim3(16, 4), dim3(32, 8)>>>(Wx0, 512, pWx0h, pWx0l, 1);
    wsplit_kernel<<<dim3(16, 4), dim3(32, 8)>>>(Wh0, 512, pWh0h, pWh0l, 1);
    wsplit_kernel<<<dim3(16, 4), dim3(32, 8)>>>(Wx1, 512, pWx1h, pWx1l, 1);
    wsplit_kernel<<<dim3(16, 4), dim3(32, 8)>>>(Wh1, 512, pWh1h, pWh1l, 1);

    // --- activation conversions ---
    convert_split_kernel<<<400, 256>>>(h0, pH0h, pH0l, 3200 * 32);
    convert_split_kernel<<<400, 256>>>(h1, pH1h, pH1l, 3200 * 32);
    build_query_kernel<<<(R_Q * 32 + 255) / 256, 256>>>(sq, h1);

    // --- projections ---
    gemm_mma_kernel<<<dim3(1, 600), 256, GEMM_SMEM>>>(pQh, pQl, pWqh, pWql, pQf, bq, 128, 0);
    gemm_kv_kernel<<<4200, 256, KV_SMEM>>>(enc, pWkvh, pWkvl, pKV, pBkv);

    // --- attention ---
    attn_kernel<<<dim3(Nd, Bd), 256, ATTN_SMEM>>>(pQf, pKV, attn_out, pCh, pCl);

    // --- combined = query@ctxW_top + ctx@Wcc + bcc ---
    gemm_mma_kernel<<<dim3(1, 600), 256, GEMM_SMEM>>>(pQh, pQl, pWth, pWtl, pComb, pBcc, 128, 0);
    gemm_mma_kernel<<<dim3(1, 600), 256, GEMM_SMEM>>>(pCh, pCl, pWcch, pWccl, pComb, (const float*)0, 128, 1);

    // --- layer 0 (gates GEMM with fused LSTM cell -> x1) ---
    gemm_mma_kernel<<<dim3(4, 25), 256, GEMM_SMEM>>>(pH0h, pH0l, pWh0h, pWh0l, pHWh, (const float*)0, 512, 0);
    agg_kernel<<<dim3(25, Bd), 512>>>(adj, pHWh, b0, pG0);
    ln_kernel<<<R_Q / 8, 256>>>(pComb, lng0, lnb0, pXh, pXl);
    gemm_gates_kernel<<<dim3(4, 600), 256, GEMM_SMEM>>>(pXh, pXl, pWx0h, pWx0l,
        pG0, c0, (const float*)0, pX1, (float*)0, (const float*)0, 0);
    ln_kernel<<<R_Q / 8, 256>>>(pX1, lng1, lnb1, pXh, pXl);

    // --- layer 1 (gates GEMM with fused cell + residual + preds partials) ---
    gemm_mma_kernel<<<dim3(4, 25), 256, GEMM_SMEM>>>(pH1h, pH1l, pWh1h, pWh1l, pHWh, (const float*)0, 512, 0);
    agg_kernel<<<dim3(25, Bd), 512>>>(adj, pHWh, b1, pG1);
    gemm_gates_kernel<<<dim3(4, 600), 256, GEMM_SMEM>>>(pXh, pXl, pWx1h, pWx1l,
        pG1, c1, pX1, (float*)0, pPP, outW, 1);
    preds_reduce_kernel<<<(R_Q + 255) / 256, 256>>>(pPP, outb, out);
}